// round 1
// baseline (speedup 1.0000x reference)
#include <cuda_runtime.h>
#include <cstdint>
#include <cstddef>

#define TB        128   // rows per block
#define NTHREADS  512
#define HID       128
#define IN_DIM    32
#define BATCH     131072

// ---------------- packed f32x2 helpers (Blackwell sm_100+) ----------------
__device__ __forceinline__ unsigned long long pk2(float lo, float hi) {
    unsigned long long r;
    asm("mov.b64 %0, {%1, %2};" : "=l"(r) : "f"(lo), "f"(hi));
    return r;
}
__device__ __forceinline__ unsigned long long fma2(unsigned long long a,
                                                   unsigned long long b,
                                                   unsigned long long c) {
    unsigned long long d;
    asm("fma.rn.f32x2 %0, %1, %2, %3;" : "=l"(d) : "l"(a), "l"(b), "l"(c));
    return d;
}
__device__ __forceinline__ float2 upk2(unsigned long long v) {
    float2 f;
    asm("mov.b64 {%0, %1}, %2;" : "=f"(f.x), "=f"(f.y) : "l"(v));
    return f;
}

// ---------------- shared memory layout (230,436 B) ----------------
struct Smem {
    float bufA[HID * TB];      // 64 KB  activations ping
    float bufB[HID * TB];      // 64 KB  activations pong
    float W1[HID * HID];       // 64 KB
    float W0[HID * IN_DIM];    // 16 KB
    union {
        float Xt[IN_DIM * TB]; // 16 KB  (input transposed; dead after layer 1)
        float W2[9 * HID];     // 4.5 KB (loaded after layer 1)
    } u;
    float b0[HID];
    float b1[HID];
    float b2[9];
};

// ---------------- 3x3 expm (scaling & squaring + Horner Taylor-10) --------
__device__ __forceinline__ void mm3(const float* A, const float* B, float* C) {
#pragma unroll
    for (int i = 0; i < 3; i++)
#pragma unroll
        for (int j = 0; j < 3; j++)
            C[3 * i + j] = fmaf(A[3 * i + 0], B[0 + j],
                           fmaf(A[3 * i + 1], B[3 + j],
                                A[3 * i + 2] * B[6 + j]));
}

__device__ void expm3(const float* A, float* E) {
    // inf-norm
    float n = 0.f;
#pragma unroll
    for (int i = 0; i < 3; i++) {
        float rs = fabsf(A[3 * i]) + fabsf(A[3 * i + 1]) + fabsf(A[3 * i + 2]);
        n = fmaxf(n, rs);
    }
    int s = 0;
    if (n > 0.5f) {
        s = (int)ceilf(log2f(n)) + 1;
        if (s < 0) s = 0;
    }
    float sc = ldexpf(1.f, -s);
    float As[9], T[9], M[9];
#pragma unroll
    for (int i = 0; i < 9; i++) {
        As[i] = A[i] * sc;
        T[i] = (i == 0 || i == 4 || i == 8) ? 1.f : 0.f;
    }
    // Horner: exp(X) = I + X(I + X/2(I + X/3(... (I + X/10) ...)))
#pragma unroll
    for (int k = 10; k >= 1; --k) {
        mm3(As, T, M);
        float inv = 1.f / (float)k;
#pragma unroll
        for (int i = 0; i < 9; i++)
            T[i] = ((i == 0 || i == 4 || i == 8) ? 1.f : 0.f) + M[i] * inv;
    }
    for (int q = 0; q < s; q++) {
        mm3(T, T, M);
#pragma unroll
        for (int i = 0; i < 9; i++) T[i] = M[i];
    }
#pragma unroll
    for (int i = 0; i < 9; i++) E[i] = T[i];
}

// ---------------- one hidden layer: src[K][TB] -> relu(W*src+b) -> dst[HID][TB]
// warp w handles 8 output neurons j = 8w..8w+7; lane handles rows 4*lane..4*lane+3
// (two f32x2 row pairs). Weight reads are warp-uniform broadcast LDS.128.
template <int K>
__device__ __forceinline__ void mlp_layer(const float* __restrict__ W,     // [HID][K]
                                          const float* __restrict__ bias,  // [HID]
                                          const float* __restrict__ src,   // [K][TB]
                                          float* __restrict__ dst,         // [HID][TB]
                                          int warp, int lane) {
    const int jbase = warp * 8;
    unsigned long long acc[8][2];
#pragma unroll
    for (int jj = 0; jj < 8; jj++) { acc[jj][0] = 0ull; acc[jj][1] = 0ull; }

#pragma unroll 2
    for (int k4 = 0; k4 < K; k4 += 4) {
        unsigned long long p[4][2];
#pragma unroll
        for (int i = 0; i < 4; i++) {
            float4 a = *(const float4*)(src + (k4 + i) * TB + lane * 4);
            p[i][0] = pk2(a.x, a.y);
            p[i][1] = pk2(a.z, a.w);
        }
#pragma unroll
        for (int jj = 0; jj < 8; jj++) {
            float4 w4 = *(const float4*)(W + (jbase + jj) * K + k4);
            unsigned long long wp;
            wp = pk2(w4.x, w4.x);
            acc[jj][0] = fma2(p[0][0], wp, acc[jj][0]);
            acc[jj][1] = fma2(p[0][1], wp, acc[jj][1]);
            wp = pk2(w4.y, w4.y);
            acc[jj][0] = fma2(p[1][0], wp, acc[jj][0]);
            acc[jj][1] = fma2(p[1][1], wp, acc[jj][1]);
            wp = pk2(w4.z, w4.z);
            acc[jj][0] = fma2(p[2][0], wp, acc[jj][0]);
            acc[jj][1] = fma2(p[2][1], wp, acc[jj][1]);
            wp = pk2(w4.w, w4.w);
            acc[jj][0] = fma2(p[3][0], wp, acc[jj][0]);
            acc[jj][1] = fma2(p[3][1], wp, acc[jj][1]);
        }
    }

#pragma unroll
    for (int jj = 0; jj < 8; jj++) {
        float b = bias[jbase + jj];
        float2 v0 = upk2(acc[jj][0]);
        float2 v1 = upk2(acc[jj][1]);
        float4 o;
        o.x = fmaxf(v0.x + b, 0.f);
        o.y = fmaxf(v0.y + b, 0.f);
        o.z = fmaxf(v1.x + b, 0.f);
        o.w = fmaxf(v1.y + b, 0.f);
        *(float4*)(dst + (jbase + jj) * TB + lane * 4) = o;
    }
}

// ---------------- main kernel: one MLP branch (rot with expm, or trz) -----
template <int OUT, bool EXPM, int COLOFF, int OUTOFF>
__global__ __launch_bounds__(NTHREADS, 1)
void mlp_kernel(const float* __restrict__ y,
                const float* __restrict__ w0, const float* __restrict__ b0,
                const float* __restrict__ w1, const float* __restrict__ b1,
                const float* __restrict__ w2, const float* __restrict__ b2,
                float* __restrict__ out) {
    extern __shared__ char smem_raw[];
    Smem& S = *reinterpret_cast<Smem*>(smem_raw);
    const int t = threadIdx.x;
    const int warp = t >> 5;
    const int lane = t & 31;
    const int r0 = blockIdx.x * TB;

    // ---- stage input transposed: y[(r0+r)*64 + COLOFF + c] -> Xt[c*TB + r]
#pragma unroll
    for (int pass = 0; pass < TB / (NTHREADS / 8); ++pass) {  // 2 passes
        int c4 = t & 7;
        int r = (t >> 3) + pass * (NTHREADS / 8);
        float4 v = *(const float4*)(y + (size_t)(r0 + r) * 64 + COLOFF + c4 * 4);
        S.u.Xt[(c4 * 4 + 0) * TB + r] = v.x;
        S.u.Xt[(c4 * 4 + 1) * TB + r] = v.y;
        S.u.Xt[(c4 * 4 + 2) * TB + r] = v.z;
        S.u.Xt[(c4 * 4 + 3) * TB + r] = v.w;
    }
    // ---- stage weights / biases (coalesced)
    for (int i = t; i < HID * IN_DIM / 4; i += NTHREADS)
        ((float4*)S.W0)[i] = ((const float4*)w0)[i];
    for (int i = t; i < HID * HID / 4; i += NTHREADS)
        ((float4*)S.W1)[i] = ((const float4*)w1)[i];
    if (t < HID) S.b0[t] = b0[t];
    else if (t < 2 * HID) S.b1[t - HID] = b1[t - HID];
    else if (t < 2 * HID + OUT) S.b2[t - 2 * HID] = b2[t - 2 * HID];
    __syncthreads();

    // ---- layer 1: Xt[32][TB] -> bufA[128][TB]
    mlp_layer<IN_DIM>(S.W0, S.b0, S.u.Xt, S.bufA, warp, lane);
    __syncthreads();

    // ---- Xt now dead: load W2 into the union
    for (int i = t; i < OUT * HID / 4; i += NTHREADS)
        ((float4*)S.u.W2)[i] = ((const float4*)w2)[i];

    // ---- layer 2: bufA -> bufB
    mlp_layer<HID>(S.W1, S.b1, S.bufA, S.bufB, warp, lane);
    __syncthreads();

    // ---- layer 3: OUT outputs per row, 4-way k-split, partials into bufA
    {
        const int p = t >> 7;        // 0..3 (constant within a warp)
        const int r = t & (TB - 1);  // row
        float o[OUT];
#pragma unroll
        for (int oo = 0; oo < OUT; oo++) o[oo] = 0.f;
        const int k0 = p * (HID / 4);
#pragma unroll 4
        for (int k = k0; k < k0 + HID / 4; ++k) {
            float a = S.bufB[k * TB + r];
#pragma unroll
            for (int oo = 0; oo < OUT; oo++)
                o[oo] = fmaf(S.u.W2[oo * HID + k], a, o[oo]);
        }
        float* scr = S.bufA;  // free during layer 3
#pragma unroll
        for (int oo = 0; oo < OUT; oo++)
            scr[(p * TB + r) * 12 + oo] = o[oo];
    }
    __syncthreads();

    // ---- reduce partials, expm (rot branch), write output
    if (t < TB) {
        const int r = t;
        const float* scr = S.bufA;
        float om[OUT];
#pragma unroll
        for (int oo = 0; oo < OUT; oo++)
            om[oo] = S.b2[oo]
                   + scr[(0 * TB + r) * 12 + oo] + scr[(1 * TB + r) * 12 + oo]
                   + scr[(2 * TB + r) * 12 + oo] + scr[(3 * TB + r) * 12 + oo];
        float* orow = out + (size_t)(r0 + r) * 12 + OUTOFF;
        if constexpr (EXPM) {
            float E[9];
            expm3(om, E);
#pragma unroll
            for (int i = 0; i < 9; i++) orow[i] = E[i];
        } else {
#pragma unroll
            for (int oo = 0; oo < OUT; oo++) orow[oo] = om[oo];
        }
    }
}

// ---------------- launch ----------------
extern "C" void kernel_launch(void* const* d_in, const int* in_sizes, int n_in,
                              void* d_out, int out_size) {
    const float* y   = (const float*)d_in[0];
    const float* ow0 = (const float*)d_in[1];
    const float* ob0 = (const float*)d_in[2];
    const float* ow1 = (const float*)d_in[3];
    const float* ob1 = (const float*)d_in[4];
    const float* ow2 = (const float*)d_in[5];
    const float* ob2 = (const float*)d_in[6];
    const float* tw0 = (const float*)d_in[7];
    const float* tb0 = (const float*)d_in[8];
    const float* tw1 = (const float*)d_in[9];
    const float* tb1 = (const float*)d_in[10];
    const float* tw2 = (const float*)d_in[11];
    const float* tb2 = (const float*)d_in[12];
    float* out = (float*)d_out;

    const size_t smem = sizeof(Smem);
    cudaFuncSetAttribute(mlp_kernel<9, true, 0, 0>,
                         cudaFuncAttributeMaxDynamicSharedMemorySize, (int)smem);
    cudaFuncSetAttribute(mlp_kernel<3, false, 32, 9>,
                         cudaFuncAttributeMaxDynamicSharedMemorySize, (int)smem);

    dim3 grid(BATCH / TB);
    mlp_kernel<9, true, 0, 0><<<grid, NTHREADS, smem>>>(
        y, ow0, ob0, ow1, ob1, ow2, ob2, out);
    mlp_kernel<3, false, 32, 9><<<grid, NTHREADS, smem>>>(
        y, tw0, tb0, tw1, tb1, tw2, tb2, out);
}